// round 12
// baseline (speedup 1.0000x reference)
#include <cuda_runtime.h>
#include <cuda_fp16.h>
#include <math.h>
#include <stdint.h>

// Problem constants
#define Bc   2
#define Tc   512
#define Cc   768
#define Hc   12
#define HDc  64
#define Vc   50304
#define Lc   12
#define Mc   (Bc * Tc)          // 1024 rows
#define BHc  (Bc * Hc)          // 24
#define EPSc 1e-5f
#define GELU_Kc 0.7978845608028654f

// ---------------- scratch (device globals; no allocations allowed) ----------
__device__ float  g_x[Mc * Cc];
__device__ float  g_ww[Vc];
__device__ float  g_xx[Mc];

__device__ __half w_attn16[Lc * 3 * Cc * Cc];
__device__ __half w_proj16[Lc * Cc * Cc];
__device__ __half w_fc16[Lc * 4 * Cc * Cc];
__device__ __half w_fc216[Lc * Cc * 4 * Cc];
__device__ __half w_wte16[(size_t)Vc * Cc];

__device__ __half g_h16[Mc * Cc];
__device__ __half g_qkv16[Mc * 3 * Cc];
__device__ __half g_y16[Mc * Cc];
__device__ __half g_fc16[Mc * 4 * Cc];
__device__ __half g_wx16[(size_t)Mc * Vc];     // head logits staging (103MB)

// ---------------- reduction helpers -----------------------------------------
__device__ __forceinline__ float warpSum(float v) {
#pragma unroll
    for (int o = 16; o; o >>= 1) v += __shfl_xor_sync(0xffffffffu, v, o);
    return v;
}
__device__ __forceinline__ float warpMin(float v) {
#pragma unroll
    for (int o = 16; o; o >>= 1) v = fminf(v, __shfl_xor_sync(0xffffffffu, v, o));
    return v;
}
__device__ float blockSum(float v, float* sm) {
    int lane = threadIdx.x & 31, wid = threadIdx.x >> 5;
    int nw = blockDim.x >> 5;
    v = warpSum(v);
    if (lane == 0) sm[wid] = v;
    __syncthreads();
    float r = (threadIdx.x < nw) ? sm[threadIdx.x] : 0.0f;
    if (wid == 0) { r = warpSum(r); if (lane == 0) sm[0] = r; }
    __syncthreads();
    float out = sm[0];
    __syncthreads();
    return out;
}
__device__ float blockMin(float v, float* sm) {
    int lane = threadIdx.x & 31, wid = threadIdx.x >> 5;
    int nw = blockDim.x >> 5;
    v = warpMin(v);
    if (lane == 0) sm[wid] = v;
    __syncthreads();
    float r = (threadIdx.x < nw) ? sm[threadIdx.x] : INFINITY;
    if (wid == 0) { r = warpMin(r); if (lane == 0) sm[0] = r; }
    __syncthreads();
    float out = sm[0];
    __syncthreads();
    return out;
}

// ---------------- low-level asm helpers --------------------------------------
__device__ __forceinline__ void cpasync16(void* smem, const void* g, int sz) {
    unsigned a = (unsigned)__cvta_generic_to_shared(smem);
    asm volatile("cp.async.cg.shared.global [%0], [%1], 16, %2;\n"
                 :: "r"(a), "l"(g), "r"(sz));
}
#define CP_COMMIT() asm volatile("cp.async.commit_group;\n")
#define CP_WAIT0()  asm volatile("cp.async.wait_group 0;\n")
#define CP_WAIT1()  asm volatile("cp.async.wait_group 1;\n")
#define CP_WAIT2()  asm volatile("cp.async.wait_group 2;\n")

__device__ __forceinline__ void ldsm4(unsigned& r0, unsigned& r1, unsigned& r2,
                                      unsigned& r3, const __half* p) {
    unsigned a = (unsigned)__cvta_generic_to_shared(p);
    asm volatile("ldmatrix.sync.aligned.m8n8.x4.shared.b16 {%0,%1,%2,%3}, [%4];\n"
                 : "=r"(r0), "=r"(r1), "=r"(r2), "=r"(r3) : "r"(a));
}
__device__ __forceinline__ void ldsm4t(unsigned& r0, unsigned& r1, unsigned& r2,
                                       unsigned& r3, const __half* p) {
    unsigned a = (unsigned)__cvta_generic_to_shared(p);
    asm volatile("ldmatrix.sync.aligned.m8n8.x4.trans.shared.b16 {%0,%1,%2,%3}, [%4];\n"
                 : "=r"(r0), "=r"(r1), "=r"(r2), "=r"(r3) : "r"(a));
}
__device__ __forceinline__ void mma16(float* c, unsigned a0, unsigned a1,
                                      unsigned a2, unsigned a3,
                                      unsigned b0, unsigned b1) {
    asm volatile(
        "mma.sync.aligned.m16n8k16.row.col.f32.f16.f16.f32 "
        "{%0,%1,%2,%3},{%4,%5,%6,%7},{%8,%9},{%0,%1,%2,%3};\n"
        : "+f"(c[0]), "+f"(c[1]), "+f"(c[2]), "+f"(c[3])
        : "r"(a0), "r"(a1), "r"(a2), "r"(a3), "r"(b0), "r"(b1));
}

__device__ __forceinline__ float geluf(float t) {
    return 0.5f * t * (1.0f + tanhf(GELU_Kc * (t + 0.044715f * t * t * t)));
}

// ---------------- f32 -> f16 convert ------------------------------------------
__global__ void f2h_kernel(const float* __restrict__ src, __half* __restrict__ dst,
                           long n2) {
    long i = (long)blockIdx.x * blockDim.x + threadIdx.x;
    long stride = (long)gridDim.x * blockDim.x;
    const float2* s2 = (const float2*)src;
    __half2* d2 = (__half2*)dst;
    for (; i < n2; i += stride) {
        float2 v = s2[i];
        d2[i] = __floats2half2_rn(v.x, v.y);
    }
}

// ---------------- embedding ---------------------------------------------------
__global__ void embed_kernel(const int* __restrict__ idx,
                             const float* __restrict__ wte,
                             const float* __restrict__ wpe,
                             float* __restrict__ x) {
    int m = blockIdx.x;
    int t = m % Tc;
    int row = idx[m];
    const float* wr = wte + (size_t)row * Cc;
    const float* pr = wpe + (size_t)t * Cc;
    float* xr = x + (size_t)m * Cc;
    for (int c = threadIdx.x; c < Cc; c += blockDim.x)
        xr[c] = wr[c] + pr[c];
}

// ---------------- layernorm (fp16 out; optional fused sum-sq) -----------------
__global__ void ln_kernel(const float* __restrict__ in, __half* __restrict__ outh,
                          float* __restrict__ xx,
                          const float* __restrict__ w, const float* __restrict__ b) {
    __shared__ float sm[32];
    int m = blockIdx.x;
    const float* row = in + (size_t)m * Cc;
    float s = 0.f, ss = 0.f;
    for (int c = threadIdx.x; c < Cc; c += blockDim.x) {
        float v = row[c];
        s += v; ss += v * v;
    }
    float tot = blockSum(s, sm);
    float tot2 = blockSum(ss, sm);
    float mean = tot / Cc;
    float var = tot2 / Cc - mean * mean;
    float rstd = rsqrtf(var + EPSc);
    __half* oh = outh + (size_t)m * Cc;
    float s2 = 0.f;
    for (int c = threadIdx.x; c < Cc; c += blockDim.x) {
        float v = (row[c] - mean) * rstd * w[c] + b[c];
        oh[c] = __float2half_rn(v);
        s2 += v * v;
    }
    if (xx) {
        float t2 = blockSum(s2, sm);
        if (threadIdx.x == 0) xx[m] = t2;
    }
}

// ---------------- 4-stage pipelined fp16 MMA GEMM (NT): out = A @ B^T ---------
// Tile: BM = MI*32, BN = NI*32.  8 warps = 2 (m) x 4 (n).
// MODE 0: +bias | 1: +bias+residual(f32) | 2: +bias+GELU | 3: plain
// OUTH: write fp16 else fp32.
template <int MODE, bool OUTH, int MI, int NI>
__global__ __launch_bounds__(256) void gemm16(
    const __half* __restrict__ A, long ldA,
    const __half* __restrict__ B, long ldB,
    const float* __restrict__ bias, const float* __restrict__ res,
    void* __restrict__ Out, long ldO,
    int K, int Nr) {
    const int BM = MI * 32, BN = NI * 32, BK = 32, BK8 = BK + 8;
    const int NB = (NI + 1) / 2;          // n16 ldsm groups per warp
    int bm = blockIdx.y * BM;
    int bn = blockIdx.x * BN;

    extern __shared__ unsigned char dyn_raw[];
    __half* As = (__half*)dyn_raw;                         // [4][BM][BK8]
    __half* Bs = As + 4 * BM * BK8;                        // [4][BN][BK8]
#define ASM_(s, r, c) As[((s) * BM + (r)) * BK8 + (c)]
#define BSM_(s, r, c) Bs[((s) * BN + (r)) * BK8 + (c)]

    const float* Res = (MODE == 1) ? res : nullptr;
    float*  OutF = OUTH ? nullptr : (float*)Out;
    __half* OutH = OUTH ? (__half*)Out : nullptr;

    int tid = threadIdx.x;
    int lane = tid & 31;
    int wid = tid >> 5;
    int g = lane >> 2;
    int tq = lane & 3;
    int wm = (wid & 1) * (MI * 16);
    int wn = (wid >> 1) * (NI * 8);
    int lrow = lane & 15;
    int lcol = (lane >> 4) * 8;

    int lr = tid >> 2;         // 0..63
    int lk = (tid & 3) * 8;

    const __half* aP0 = A + (size_t)(bm + lr) * ldA + lk;
    const __half* aP1 = aP0 + (size_t)64 * ldA;
    int brow0 = bn + lr, brow1 = bn + lr + 64;
    int szB0 = (brow0 < Nr) ? 16 : 0;
    int szB1 = (brow1 < Nr) ? 16 : 0;
    const __half* bP0 = B + (size_t)(szB0 ? brow0 : 0) * ldB + lk;
    const __half* bP1 = B + (size_t)(szB1 ? brow1 : 0) * ldB + lk;

    float acc[MI][NI][4];
#pragma unroll
    for (int i = 0; i < MI; i++)
#pragma unroll
        for (int j = 0; j < NI; j++)
#pragma unroll
            for (int r = 0; r < 4; r++) acc[i][j][r] = 0.f;

    int nk = K / BK;

    auto load_tile = [&](int st, int kt) {
        int k0 = kt * BK;
        cpasync16(&ASM_(st, lr, lk), aP0 + k0, 16);
        if (MI == 4) cpasync16(&ASM_(st, lr + 64, lk), aP1 + k0, 16);
        cpasync16(&BSM_(st, lr, lk), bP0 + k0, szB0);
        if (NI == 4) cpasync16(&BSM_(st, lr + 64, lk), bP1 + k0, szB1);
        CP_COMMIT();
    };

    // prologue: 3 tiles in flight
    load_tile(0, 0);
    if (nk > 1) load_tile(1, 1);
    if (nk > 2) load_tile(2, 2);

    for (int kt = 0; kt < nk; kt++) {
        int pend = nk - 1 - kt;
        if (pend >= 2) { CP_WAIT2(); }
        else if (pend == 1) { CP_WAIT1(); }
        else { CP_WAIT0(); }
        __syncthreads();
        if (kt + 3 < nk) load_tile((kt + 3) & 3, kt + 3);
        int buf = kt & 3;

#pragma unroll
        for (int kp = 0; kp < 2; kp++) {
            unsigned af[MI][4];
#pragma unroll
            for (int mi = 0; mi < MI; mi++)
                ldsm4(af[mi][0], af[mi][1], af[mi][2], af[mi][3],
                      &ASM_(buf, wm + mi * 16 + lrow, kp * 16 + lcol));
            unsigned bf[NB][4];
#pragma unroll
            for (int nb = 0; nb < NB; nb++)
                ldsm4(bf[nb][0], bf[nb][1], bf[nb][2], bf[nb][3],
                      &BSM_(buf, wn + nb * 16 + lrow, kp * 16 + lcol));
#pragma unroll
            for (int mi = 0; mi < MI; mi++)
#pragma unroll
                for (int ni = 0; ni < NI; ni++) {
                    int nb = ni >> 1, wh = ni & 1;
                    mma16(acc[mi][ni],
                          af[mi][0], af[mi][1], af[mi][2], af[mi][3],
                          bf[nb][wh ? 1 : 0], bf[nb][wh ? 3 : 2]);
                }
        }
    }

    // epilogue
#pragma unroll
    for (int mi = 0; mi < MI; mi++) {
        int m = bm + wm + mi * 16 + g;
#pragma unroll
        for (int ni = 0; ni < NI; ni++) {
            int n = bn + wn + ni * 8 + tq * 2;
            if (n >= Nr) continue;
            float v0 = acc[mi][ni][0], v1 = acc[mi][ni][1];
            float v2 = acc[mi][ni][2], v3 = acc[mi][ni][3];
            if (MODE != 3) {
                float b0 = bias[n], b1 = bias[n + 1];
                v0 += b0; v1 += b1; v2 += b0; v3 += b1;
            }
            if (MODE == 1) {
                v0 += Res[(size_t)m * ldO + n];
                v1 += Res[(size_t)m * ldO + n + 1];
                v2 += Res[(size_t)(m + 8) * ldO + n];
                v3 += Res[(size_t)(m + 8) * ldO + n + 1];
            }
            if (MODE == 2) { v0 = geluf(v0); v1 = geluf(v1); v2 = geluf(v2); v3 = geluf(v3); }
            if (OUTH) {
                *(__half2*)(OutH + (size_t)m * ldO + n) = __floats2half2_rn(v0, v1);
                *(__half2*)(OutH + (size_t)(m + 8) * ldO + n) = __floats2half2_rn(v2, v3);
            } else {
                *(float2*)(OutF + (size_t)m * ldO + n) = make_float2(v0, v1);
                *(float2*)(OutF + (size_t)(m + 8) * ldO + n) = make_float2(v2, v3);
            }
        }
    }
#undef ASM_
#undef BSM_
}

// ---------------- fused flash attention ---------------------------------------
__global__ __launch_bounds__(128) void flash_kernel(const __half* __restrict__ qkv,
                                                    __half* __restrict__ y) {
    int qt = blockIdx.x, z = blockIdx.y;
    int b = z / Hc, h = z - b * Hc;
    const __half* base = qkv + (size_t)b * Tc * 3 * Cc;
    const __half* Qg = base + (size_t)qt * 64 * 3 * Cc + h * HDc;
    const __half* Kg = base + Cc + h * HDc;
    const __half* Vg = base + 2 * Cc + h * HDc;

    __shared__ __half Qs[64][72];
    __shared__ __half Ks[2][64][72];
    __shared__ __half Vs[2][64][72];

    int tid = threadIdx.x, lane = tid & 31, w = tid >> 5;
    int g = lane >> 2, tq = lane & 3;
    int lrow = lane & 15, lcol = (lane >> 4) * 8;

    for (int c = tid; c < 512; c += 128) {
        int r = c >> 3, c8 = (c & 7) * 8;
        cpasync16(&Qs[r][c8], Qg + (size_t)r * 3 * Cc + c8, 16);
        cpasync16(&Ks[0][r][c8], Kg + (size_t)r * 3 * Cc + c8, 16);
        cpasync16(&Vs[0][r][c8], Vg + (size_t)r * 3 * Cc + c8, 16);
    }
    CP_COMMIT();
    CP_WAIT0();
    __syncthreads();

    unsigned qf[4][4];
#pragma unroll
    for (int kc = 0; kc < 4; kc++)
        ldsm4(qf[kc][0], qf[kc][1], qf[kc][2], qf[kc][3],
              &Qs[w * 16 + lrow][kc * 16 + lcol]);

    float o[8][4];
#pragma unroll
    for (int i = 0; i < 8; i++)
#pragma unroll
        for (int r = 0; r < 4; r++) o[i][r] = 0.f;
    float m0 = -INFINITY, m1 = -INFINITY, l0 = 0.f, l1 = 0.f;

    int buf = 0;
    for (int j = 0; j <= qt; j++) {
        if (j + 1 <= qt) {
            for (int c = tid; c < 512; c += 128) {
                int r = c >> 3, c8 = (c & 7) * 8;
                cpasync16(&Ks[buf ^ 1][r][c8],
                          Kg + (size_t)((j + 1) * 64 + r) * 3 * Cc + c8, 16);
                cpasync16(&Vs[buf ^ 1][r][c8],
                          Vg + (size_t)((j + 1) * 64 + r) * 3 * Cc + c8, 16);
            }
            CP_COMMIT();
            CP_WAIT1();
        } else {
            CP_WAIT0();
        }
        __syncthreads();

        float s[8][4];
#pragma unroll
        for (int i = 0; i < 8; i++)
#pragma unroll
            for (int r = 0; r < 4; r++) s[i][r] = 0.f;
#pragma unroll
        for (int kc = 0; kc < 4; kc++) {
            unsigned kf[4][4];
#pragma unroll
            for (int nb = 0; nb < 4; nb++)
                ldsm4(kf[nb][0], kf[nb][1], kf[nb][2], kf[nb][3],
                      &Ks[buf][nb * 16 + lrow][kc * 16 + lcol]);
#pragma unroll
            for (int nb = 0; nb < 4; nb++) {
                mma16(s[nb * 2], qf[kc][0], qf[kc][1], qf[kc][2], qf[kc][3],
                      kf[nb][0], kf[nb][2]);
                mma16(s[nb * 2 + 1], qf[kc][0], qf[kc][1], qf[kc][2], qf[kc][3],
                      kf[nb][1], kf[nb][3]);
            }
        }
#pragma unroll
        for (int i = 0; i < 8; i++)
#pragma unroll
            for (int r = 0; r < 4; r++) s[i][r] *= 0.125f;
        if (j == qt) {
            int r0 = w * 16 + g, r1 = r0 + 8;
#pragma unroll
            for (int nt = 0; nt < 8; nt++) {
                int c0 = nt * 8 + tq * 2;
                if (c0 > r0) s[nt][0] = -1e30f;
                if (c0 + 1 > r0) s[nt][1] = -1e30f;
                if (c0 > r1) s[nt][2] = -1e30f;
                if (c0 + 1 > r1) s[nt][3] = -1e30f;
            }
        }
        float tm0 = -INFINITY, tm1 = -INFINITY;
#pragma unroll
        for (int nt = 0; nt < 8; nt++) {
            tm0 = fmaxf(tm0, fmaxf(s[nt][0], s[nt][1]));
            tm1 = fmaxf(tm1, fmaxf(s[nt][2], s[nt][3]));
        }
        tm0 = fmaxf(tm0, __shfl_xor_sync(0xffffffffu, tm0, 1));
        tm0 = fmaxf(tm0, __shfl_xor_sync(0xffffffffu, tm0, 2));
        tm1 = fmaxf(tm1, __shfl_xor_sync(0xffffffffu, tm1, 1));
        tm1 = fmaxf(tm1, __shfl_xor_sync(0xffffffffu, tm1, 2));
        float mn0 = fmaxf(m0, tm0), mn1 = fmaxf(m1, tm1);
        float a0 = __expf(m0 - mn0), a1 = __expf(m1 - mn1);
        m0 = mn0; m1 = mn1;

        float rs0 = 0.f, rs1 = 0.f;
        unsigned pa[4][4];
#pragma unroll
        for (int nt = 0; nt < 8; nt++) {
            float p0 = __expf(s[nt][0] - mn0);
            float p1 = __expf(s[nt][1] - mn0);
            float p2 = __expf(s[nt][2] - mn1);
            float p3 = __expf(s[nt][3] - mn1);
            rs0 += p0 + p1; rs1 += p2 + p3;
            int kc2 = nt >> 1, hh = (nt & 1) * 2;
            __half2 h01 = __floats2half2_rn(p0, p1);
            __half2 h23 = __floats2half2_rn(p2, p3);
            pa[kc2][hh]     = *(unsigned*)&h01;
            pa[kc2][hh + 1] = *(unsigned*)&h23;
        }
        rs0 += __shfl_xor_sync(0xffffffffu, rs0, 1);
        rs0 += __shfl_xor_sync(0xffffffffu, rs0, 2);
        rs1 += __shfl_xor_sync(0xffffffffu, rs1, 1);
        rs1 += __shfl_xor_sync(0xffffffffu, rs1, 2);
        l0 = l0 * a0 + rs0;
        l1 = l1 * a1 + rs1;
#pragma unroll
        for (int nt = 0; nt < 8; nt++) {
            o[nt][0] *= a0; o[nt][1] *= a0;
            o[nt][2] *= a1; o[nt][3] *= a1;
        }
#pragma unroll
        for (int kc2 = 0; kc2 < 4; kc2++) {
#pragma unroll
            for (int dn = 0; dn < 4; dn++) {
                unsigned v0, v1, v2, v3;
                ldsm4t(v0, v1, v2, v3,
                       &Vs[buf][kc2 * 16 + lrow][dn * 16 + lcol]);
                mma16(o[dn * 2], pa[kc2][0], pa[kc2][1], pa[kc2][2], pa[kc2][3], v0, v1);
                mma16(o[dn * 2 + 1], pa[kc2][0], pa[kc2][1], pa[kc2][2], pa[kc2][3], v2, v3);
            }
        }
        __syncthreads();
        buf ^= 1;
    }

    float il0 = 1.0f / l0, il1 = 1.0f / l1;
    int row0 = qt * 64 + w * 16 + g;
    __half* yp = y + ((size_t)(b * Tc + row0)) * Cc + h * HDc;
#pragma unroll
    for (int nt = 0; nt < 8; nt++) {
        int col = nt * 8 + tq * 2;
        *(__half2*)(yp + col) = __floats2half2_rn(o[nt][0] * il0, o[nt][1] * il0);
        *(__half2*)(yp + (size_t)8 * Cc + col) =
            __floats2half2_rn(o[nt][2] * il1, o[nt][3] * il1);
    }
}

// ---------------- head helpers ------------------------------------------------
__global__ void ww_kernel(const float* __restrict__ wte, float* __restrict__ ww) {
    __shared__ float sm[32];
    int v = blockIdx.x;
    const float* row = wte + (size_t)v * Cc;
    float s = 0.f;
    for (int c = threadIdx.x; c < Cc; c += blockDim.x) { float t = row[c]; s += t * t; }
    float tot = blockSum(s, sm);
    if (threadIdx.x == 0) ww[v] = tot;
}

// dist: 2-MUFU-per-element formulation.
// p = r^-768 = 2^(-768*(log2 d - log2 dmin)).
// Phase A: t = log2(d) staged fp32 into out row; min-reduce t.
// Phase B: p = exp2(fma(t,-768,768*tmin)); sum; stage p fp16 into wx row.
// Phase C: logit = ln(p*invTot + floorp) -> out row (fp32).
__global__ __launch_bounds__(512) void dist_kernel(__half* __restrict__ wx,
                                                   float* __restrict__ out,
                                                   const float* __restrict__ ww,
                                                   const float* __restrict__ xx) {
    __shared__ float sm[32];
    int m = blockIdx.x;
    __half2* row2 = (__half2*)(wx + (size_t)m * Vc);
    float2* trow2 = (float2*)(out + (size_t)m * Vc);
    const float2* ww2 = (const float2*)ww;
    float xxm = xx[m];
    const int N2 = Vc / 2;

    // phase A: t = log2(d), block min
    float mn = INFINITY;
    for (int i = threadIdx.x; i < N2; i += 512) {
        float2 wv = ww2[i];
        float2 xv = __half22float2(row2[i]);
        float d0 = fmaf(-2.0f, xv.x, wv.x + xxm);
        float d1 = fmaf(-2.0f, xv.y, wv.y + xxm);
        float t0 = __log2f(d0);
        float t1 = __log2f(d1);
        trow2[i] = make_float2(t0, t1);
        mn = fminf(mn, fminf(t0, t1));
    }
    float TMIN = blockMin(mn, sm);
    float base = 768.0f * TMIN;

    // phase B: p = 2^(-768 t + base), sum, stage fp16
    float lsum = 0.f;
    for (int i = threadIdx.x; i < N2; i += 512) {
        float2 tv = trow2[i];
        float p0 = exp2f(fmaf(tv.x, -768.0f, base));
        float p1 = exp2f(fmaf(tv.y, -768.0f, base));
        lsum += p0 + p1;
        row2[i] = __floats2half2_rn(p0, p1);
    }
    float TOT = blockSum(lsum, sm);
    float invTot = 1.0f / TOT;
    const float floorp = 0.01f / 50304.0f;

    // phase C: logits
    for (int i = threadIdx.x; i < N2; i += 512) {
        float2 pv = __half22float2(row2[i]);
        float l0 = __logf(fmaf(pv.x, invTot, floorp));
        float l1 = __logf(fmaf(pv.y, invTot, floorp));
        trow2[i] = make_float2(l0, l1);
    }
}

// ---------------- launch ------------------------------------------------------
extern "C" void kernel_launch(void* const* d_in, const int* in_sizes, int n_in,
                              void* d_out, int out_size) {
    const int*   idx    = (const int*)d_in[0];
    const float* wte    = (const float*)d_in[1];
    const float* wpe    = (const float*)d_in[2];
    const float* ln1_w  = (const float*)d_in[3];
    const float* ln1_b  = (const float*)d_in[4];
    const float* attn_w = (const float*)d_in[5];
    const float* attn_b = (const float*)d_in[6];
    const float* proj_w = (const float*)d_in[7];
    const float* proj_b = (const float*)d_in[8];
    const float* ln2_w  = (const float*)d_in[9];
    const float* ln2_b  = (const float*)d_in[10];
    const float* fc_w   = (const float*)d_in[11];
    const float* fc_b   = (const float*)d_in[12];
    const float* fc2_w  = (const float*)d_in[13];
    const float* fc2_b  = (const float*)d_in[14];
    const float* lnf_w  = (const float*)d_in[15];
    const float* lnf_b  = (const float*)d_in[16];
    float* out = (float*)d_out;

    float *x, *ww, *xx;
    __half *attn16, *proj16, *fcw16, *fc2w16, *wte16;
    __half *h16, *qkv16, *y16, *fcact16, *wx16;
    cudaGetSymbolAddress((void**)&x, g_x);
    cudaGetSymbolAddress((void**)&ww, g_ww);
    cudaGetSymbolAddress((void**)&xx, g_xx);
    cudaGetSymbolAddress((void**)&attn16, w_attn16);
    cudaGetSymbolAddress((void**)&proj16, w_proj16);
    cudaGetSymbolAddress((void**)&fcw16, w_fc16);
    cudaGetSymbolAddress((void**)&fc2w16, w_fc216);
    cudaGetSymbolAddress((void**)&wte16, w_wte16);
    cudaGetSymbolAddress((void**)&h16, g_h16);
    cudaGetSymbolAddress((void**)&qkv16, g_qkv16);
    cudaGetSymbolAddress((void**)&y16, g_y16);
    cudaGetSymbolAddress((void**)&fcact16, g_fc16);
    cudaGetSymbolAddress((void**)&wx16, g_wx16);

    const int S44 = 4 * (128 + 128) * 40 * 2;   // 81920 bytes
    const int S22 = 4 * (64 + 64) * 40 * 2;     // 40960 bytes
    cudaFuncSetAttribute(gemm16<0, true, 4, 4>,
                         cudaFuncAttributeMaxDynamicSharedMemorySize, S44);
    cudaFuncSetAttribute(gemm16<2, true, 4, 4>,
                         cudaFuncAttributeMaxDynamicSharedMemorySize, S44);
    cudaFuncSetAttribute(gemm16<3, true, 4, 4>,
                         cudaFuncAttributeMaxDynamicSharedMemorySize, S44);
    cudaFuncSetAttribute(gemm16<1, false, 2, 2>,
                         cudaFuncAttributeMaxDynamicSharedMemorySize, S22);

    // weight conversions
    f2h_kernel<<<4096, 256>>>(attn_w, attn16, (long)Lc * 3 * Cc * Cc / 2);
    f2h_kernel<<<4096, 256>>>(proj_w, proj16, (long)Lc * Cc * Cc / 2);
    f2h_kernel<<<4096, 256>>>(fc_w, fcw16, (long)Lc * 4 * Cc * Cc / 2);
    f2h_kernel<<<4096, 256>>>(fc2_w, fc2w16, (long)Lc * Cc * 4 * Cc / 2);
    f2h_kernel<<<4096, 256>>>(wte, wte16, (long)Vc * Cc / 2);

    embed_kernel<<<Mc, 256>>>(idx, wte, wpe, x);
    ww_kernel<<<Vc, 128>>>(wte, ww);

    for (int l = 0; l < Lc; l++) {
        const float* l1w = ln1_w + (size_t)l * Cc;
        const float* l1b = ln1_b + (size_t)l * Cc;
        const __half* aw = attn16 + (size_t)l * 3 * Cc * Cc;
        const float* ab  = attn_b + (size_t)l * 3 * Cc;
        const __half* pw = proj16 + (size_t)l * Cc * Cc;
        const float* pb  = proj_b + (size_t)l * Cc;
        const float* l2w = ln2_w + (size_t)l * Cc;
        const float* l2b = ln2_b + (size_t)l * Cc;
        const __half* fw = fcw16 + (size_t)l * 4 * Cc * Cc;
        const float* fb  = fc_b + (size_t)l * 4 * Cc;
        const __half* f2w = fc2w16 + (size_t)l * Cc * 4 * Cc;
        const float* f2b = fc2_b + (size_t)l * Cc;

        ln_kernel<<<Mc, 256>>>(x, h16, nullptr, l1w, l1b);

        // qkv16 = h @ attn_w^T + b   [1024, 2304]
        gemm16<0, true, 4, 4><<<dim3(18, 8), 256, S44>>>(
            h16, Cc, aw, Cc, ab, nullptr, qkv16, 3 * Cc, Cc, 3 * Cc);

        // fused attention -> y16
        flash_kernel<<<dim3(8, BHc), 128>>>(qkv16, y16);

        // x = x + y @ proj_w^T + proj_b   (fp32 out), 64x64 tiles: grid 192
        gemm16<1, false, 2, 2><<<dim3(12, 16), 256, S22>>>(
            y16, Cc, pw, Cc, pb, x, x, Cc, Cc, Cc);

        ln_kernel<<<Mc, 256>>>(x, h16, nullptr, l2w, l2b);

        // fc16 = gelu(h @ fc_w^T + fc_b)  [1024, 3072]
        gemm16<2, true, 4, 4><<<dim3(24, 8), 256, S44>>>(
            h16, Cc, fw, Cc, fb, nullptr, fcact16, 4 * Cc, Cc, 4 * Cc);

        // x = x + fc @ fc2_w^T + fc2_b   64x64 tiles: grid 192
        gemm16<1, false, 2, 2><<<dim3(12, 16), 256, S22>>>(
            fcact16, 4 * Cc, f2w, 4 * Cc, f2b, x, x, Cc, 4 * Cc, Cc);
    }

    // final LN (+ fused xx) + head
    ln_kernel<<<Mc, 256>>>(x, h16, xx, lnf_w, lnf_b);

    // wx16 = h @ wte^T  [1024, 50304] (fp16 out)
    gemm16<3, true, 4, 4><<<dim3(Vc / 128, 8), 256, S44>>>(
        h16, Cc, wte16, Cc, nullptr, nullptr, wx16, Vc, Cc, Vc);

    dist_kernel<<<Mc, 512>>>(wx16, out, ww, xx);
}

// round 13
// speedup vs baseline: 1.0595x; 1.0595x over previous
#include <cuda_runtime.h>
#include <cuda_fp16.h>
#include <math.h>
#include <stdint.h>

// Problem constants
#define Bc   2
#define Tc   512
#define Cc   768
#define Hc   12
#define HDc  64
#define Vc   50304
#define Lc   12
#define Mc   (Bc * Tc)          // 1024 rows
#define BHc  (Bc * Hc)          // 24
#define EPSc 1e-5f
#define GELU_Kc 0.7978845608028654f

// ---------------- scratch (device globals; no allocations allowed) ----------
__device__ float  g_x[Mc * Cc];
__device__ float  g_ww[Vc];
__device__ float  g_xx[Mc];

__device__ __half w_attn16[Lc * 3 * Cc * Cc];
__device__ __half w_proj16[Lc * Cc * Cc];
__device__ __half w_fc16[Lc * 4 * Cc * Cc];
__device__ __half w_fc216[Lc * Cc * 4 * Cc];
__device__ __half w_wte16[(size_t)Vc * Cc];

__device__ __half g_h16[Mc * Cc];
__device__ __half g_qkv16[Mc * 3 * Cc];
__device__ __half g_y16[Mc * Cc];
__device__ __half g_fc16[Mc * 4 * Cc];
__device__ __half g_wx16[(size_t)Mc * Vc];     // head logits staging (103MB)

// ---------------- reduction helpers -----------------------------------------
__device__ __forceinline__ float warpSum(float v) {
#pragma unroll
    for (int o = 16; o; o >>= 1) v += __shfl_xor_sync(0xffffffffu, v, o);
    return v;
}
__device__ __forceinline__ float warpMin(float v) {
#pragma unroll
    for (int o = 16; o; o >>= 1) v = fminf(v, __shfl_xor_sync(0xffffffffu, v, o));
    return v;
}
__device__ float blockSum(float v, float* sm) {
    int lane = threadIdx.x & 31, wid = threadIdx.x >> 5;
    int nw = blockDim.x >> 5;
    v = warpSum(v);
    if (lane == 0) sm[wid] = v;
    __syncthreads();
    float r = (threadIdx.x < nw) ? sm[threadIdx.x] : 0.0f;
    if (wid == 0) { r = warpSum(r); if (lane == 0) sm[0] = r; }
    __syncthreads();
    float out = sm[0];
    __syncthreads();
    return out;
}
__device__ float blockMin(float v, float* sm) {
    int lane = threadIdx.x & 31, wid = threadIdx.x >> 5;
    int nw = blockDim.x >> 5;
    v = warpMin(v);
    if (lane == 0) sm[wid] = v;
    __syncthreads();
    float r = (threadIdx.x < nw) ? sm[threadIdx.x] : INFINITY;
    if (wid == 0) { r = warpMin(r); if (lane == 0) sm[0] = r; }
    __syncthreads();
    float out = sm[0];
    __syncthreads();
    return out;
}

// ---------------- low-level asm helpers --------------------------------------
__device__ __forceinline__ void cpasync16(void* smem, const void* g, int sz) {
    unsigned a = (unsigned)__cvta_generic_to_shared(smem);
    asm volatile("cp.async.cg.shared.global [%0], [%1], 16, %2;\n"
                 :: "r"(a), "l"(g), "r"(sz));
}
#define CP_COMMIT() asm volatile("cp.async.commit_group;\n")
#define CP_WAIT0()  asm volatile("cp.async.wait_group 0;\n")
#define CP_WAIT1()  asm volatile("cp.async.wait_group 1;\n")

__device__ __forceinline__ void ldsm4(unsigned& r0, unsigned& r1, unsigned& r2,
                                      unsigned& r3, const __half* p) {
    unsigned a = (unsigned)__cvta_generic_to_shared(p);
    asm volatile("ldmatrix.sync.aligned.m8n8.x4.shared.b16 {%0,%1,%2,%3}, [%4];\n"
                 : "=r"(r0), "=r"(r1), "=r"(r2), "=r"(r3) : "r"(a));
}
__device__ __forceinline__ void ldsm4t(unsigned& r0, unsigned& r1, unsigned& r2,
                                       unsigned& r3, const __half* p) {
    unsigned a = (unsigned)__cvta_generic_to_shared(p);
    asm volatile("ldmatrix.sync.aligned.m8n8.x4.trans.shared.b16 {%0,%1,%2,%3}, [%4];\n"
                 : "=r"(r0), "=r"(r1), "=r"(r2), "=r"(r3) : "r"(a));
}
__device__ __forceinline__ void mma16(float* c, unsigned a0, unsigned a1,
                                      unsigned a2, unsigned a3,
                                      unsigned b0, unsigned b1) {
    asm volatile(
        "mma.sync.aligned.m16n8k16.row.col.f32.f16.f16.f32 "
        "{%0,%1,%2,%3},{%4,%5,%6,%7},{%8,%9},{%0,%1,%2,%3};\n"
        : "+f"(c[0]), "+f"(c[1]), "+f"(c[2]), "+f"(c[3])
        : "r"(a0), "r"(a1), "r"(a2), "r"(a3), "r"(b0), "r"(b1));
}

__device__ __forceinline__ float geluf(float t) {
    return 0.5f * t * (1.0f + tanhf(GELU_Kc * (t + 0.044715f * t * t * t)));
}

// ---------------- f32 -> f16 convert ------------------------------------------
__global__ void f2h_kernel(const float* __restrict__ src, __half* __restrict__ dst,
                           long n2) {
    long i = (long)blockIdx.x * blockDim.x + threadIdx.x;
    long stride = (long)gridDim.x * blockDim.x;
    const float2* s2 = (const float2*)src;
    __half2* d2 = (__half2*)dst;
    for (; i < n2; i += stride) {
        float2 v = s2[i];
        d2[i] = __floats2half2_rn(v.x, v.y);
    }
}

// ---------------- embedding ---------------------------------------------------
__global__ void embed_kernel(const int* __restrict__ idx,
                             const float* __restrict__ wte,
                             const float* __restrict__ wpe,
                             float* __restrict__ x) {
    int m = blockIdx.x;
    int t = m % Tc;
    int row = idx[m];
    const float* wr = wte + (size_t)row * Cc;
    const float* pr = wpe + (size_t)t * Cc;
    float* xr = x + (size_t)m * Cc;
    for (int c = threadIdx.x; c < Cc; c += blockDim.x)
        xr[c] = wr[c] + pr[c];
}

// ---------------- layernorm: warp-per-row, no __syncthreads -------------------
// 128 threads = 4 warps = 4 rows per block; grid = Mc/4.
__global__ __launch_bounds__(128) void ln_kernel(
    const float* __restrict__ in, __half* __restrict__ outh,
    float* __restrict__ xx,
    const float* __restrict__ w, const float* __restrict__ b) {
    int warp = threadIdx.x >> 5, lane = threadIdx.x & 31;
    int m = blockIdx.x * 4 + warp;
    const float4* r4 = (const float4*)(in + (size_t)m * Cc);
    const float4* w4 = (const float4*)w;
    const float4* b4 = (const float4*)b;

    float4 v[6];
    float s = 0.f, ss = 0.f;
#pragma unroll
    for (int i = 0; i < 6; i++) {
        v[i] = r4[lane + 32 * i];
        s += v[i].x + v[i].y + v[i].z + v[i].w;
        ss += v[i].x * v[i].x + v[i].y * v[i].y + v[i].z * v[i].z + v[i].w * v[i].w;
    }
    s = warpSum(s);
    ss = warpSum(ss);
    const float invC = 1.0f / Cc;
    float mean = s * invC;
    float var = ss * invC - mean * mean;
    float rstd = rsqrtf(var + EPSc);

    __half2* o2 = (__half2*)(outh + (size_t)m * Cc);
    float s2 = 0.f;
#pragma unroll
    for (int i = 0; i < 6; i++) {
        float4 wv = w4[lane + 32 * i];
        float4 bv = b4[lane + 32 * i];
        float a0 = (v[i].x - mean) * rstd * wv.x + bv.x;
        float a1 = (v[i].y - mean) * rstd * wv.y + bv.y;
        float a2 = (v[i].z - mean) * rstd * wv.z + bv.z;
        float a3 = (v[i].w - mean) * rstd * wv.w + bv.w;
        o2[2 * (lane + 32 * i)]     = __floats2half2_rn(a0, a1);
        o2[2 * (lane + 32 * i) + 1] = __floats2half2_rn(a2, a3);
        s2 += a0 * a0 + a1 * a1 + a2 * a2 + a3 * a3;
    }
    if (xx) {
        s2 = warpSum(s2);
        if (lane == 0) xx[m] = s2;
    }
}

// ---------------- 3-stage pipelined fp16 MMA GEMM (NT): out = A @ B^T ---------
// Tile: BM = MI*32, BN = NI*32.  8 warps = 2 (m) x 4 (n).  smem 61KB -> 2 CTA/SM.
// MODE 0: +bias | 1: +bias+residual(f32) | 2: +bias+GELU | 3: plain
// OUTH: write fp16 else fp32.
template <int MODE, bool OUTH, int MI, int NI>
__global__ __launch_bounds__(256) void gemm16(
    const __half* __restrict__ A, long ldA,
    const __half* __restrict__ B, long ldB,
    const float* __restrict__ bias, const float* __restrict__ res,
    void* __restrict__ Out, long ldO,
    int K, int Nr) {
    const int BM = MI * 32, BN = NI * 32, BK = 32, BK8 = BK + 8;
    const int NB = (NI + 1) / 2;          // n16 ldsm groups per warp
    int bm = blockIdx.y * BM;
    int bn = blockIdx.x * BN;

    extern __shared__ unsigned char dyn_raw[];
    __half* As = (__half*)dyn_raw;                         // [3][BM][BK8]
    __half* Bs = As + 3 * BM * BK8;                        // [3][BN][BK8]
#define ASM_(s, r, c) As[((s) * BM + (r)) * BK8 + (c)]
#define BSM_(s, r, c) Bs[((s) * BN + (r)) * BK8 + (c)]

    const float* Res = (MODE == 1) ? res : nullptr;
    float*  OutF = OUTH ? nullptr : (float*)Out;
    __half* OutH = OUTH ? (__half*)Out : nullptr;

    int tid = threadIdx.x;
    int lane = tid & 31;
    int wid = tid >> 5;
    int g = lane >> 2;
    int tq = lane & 3;
    int wm = (wid & 1) * (MI * 16);
    int wn = (wid >> 1) * (NI * 8);
    int lrow = lane & 15;
    int lcol = (lane >> 4) * 8;

    int lr = tid >> 2;         // 0..63
    int lk = (tid & 3) * 8;

    const __half* aP0 = A + (size_t)(bm + lr) * ldA + lk;
    const __half* aP1 = aP0 + (size_t)64 * ldA;
    int brow0 = bn + lr, brow1 = bn + lr + 64;
    int szB0 = (brow0 < Nr) ? 16 : 0;
    int szB1 = (brow1 < Nr) ? 16 : 0;
    const __half* bP0 = B + (size_t)(szB0 ? brow0 : 0) * ldB + lk;
    const __half* bP1 = B + (size_t)(szB1 ? brow1 : 0) * ldB + lk;

    float acc[MI][NI][4];
#pragma unroll
    for (int i = 0; i < MI; i++)
#pragma unroll
        for (int j = 0; j < NI; j++)
#pragma unroll
            for (int r = 0; r < 4; r++) acc[i][j][r] = 0.f;

    int nk = K / BK;

    auto load_tile = [&](int st, int kt) {
        int k0 = kt * BK;
        cpasync16(&ASM_(st, lr, lk), aP0 + k0, 16);
        if (MI == 4) cpasync16(&ASM_(st, lr + 64, lk), aP1 + k0, 16);
        cpasync16(&BSM_(st, lr, lk), bP0 + k0, szB0);
        if (NI == 4) cpasync16(&BSM_(st, lr + 64, lk), bP1 + k0, szB1);
        CP_COMMIT();
    };

    // prologue: 2 tiles in flight
    load_tile(0, 0);
    if (nk > 1) load_tile(1, 1);

    for (int kt = 0; kt < nk; kt++) {
        if (kt + 1 < nk) { CP_WAIT1(); } else { CP_WAIT0(); }
        __syncthreads();
        // load (kt+2) -> buffer (kt+2)%3 == (kt-1)%3; compute of kt-1 finished
        // in all warps before this barrier, so single sync is safe.
        if (kt + 2 < nk) load_tile((kt + 2) % 3, kt + 2);
        int buf = kt % 3;

#pragma unroll
        for (int kp = 0; kp < 2; kp++) {
            unsigned af[MI][4];
#pragma unroll
            for (int mi = 0; mi < MI; mi++)
                ldsm4(af[mi][0], af[mi][1], af[mi][2], af[mi][3],
                      &ASM_(buf, wm + mi * 16 + lrow, kp * 16 + lcol));
            unsigned bf[NB][4];
#pragma unroll
            for (int nb = 0; nb < NB; nb++)
                ldsm4(bf[nb][0], bf[nb][1], bf[nb][2], bf[nb][3],
                      &BSM_(buf, wn + nb * 16 + lrow, kp * 16 + lcol));
#pragma unroll
            for (int mi = 0; mi < MI; mi++)
#pragma unroll
                for (int ni = 0; ni < NI; ni++) {
                    int nb = ni >> 1, wh = ni & 1;
                    mma16(acc[mi][ni],
                          af[mi][0], af[mi][1], af[mi][2], af[mi][3],
                          bf[nb][wh ? 1 : 0], bf[nb][wh ? 3 : 2]);
                }
        }
    }

    // epilogue
#pragma unroll
    for (int mi = 0; mi < MI; mi++) {
        int m = bm + wm + mi * 16 + g;
#pragma unroll
        for (int ni = 0; ni < NI; ni++) {
            int n = bn + wn + ni * 8 + tq * 2;
            if (n >= Nr) continue;
            float v0 = acc[mi][ni][0], v1 = acc[mi][ni][1];
            float v2 = acc[mi][ni][2], v3 = acc[mi][ni][3];
            if (MODE != 3) {
                float b0 = bias[n], b1 = bias[n + 1];
                v0 += b0; v1 += b1; v2 += b0; v3 += b1;
            }
            if (MODE == 1) {
                v0 += Res[(size_t)m * ldO + n];
                v1 += Res[(size_t)m * ldO + n + 1];
                v2 += Res[(size_t)(m + 8) * ldO + n];
                v3 += Res[(size_t)(m + 8) * ldO + n + 1];
            }
            if (MODE == 2) { v0 = geluf(v0); v1 = geluf(v1); v2 = geluf(v2); v3 = geluf(v3); }
            if (OUTH) {
                *(__half2*)(OutH + (size_t)m * ldO + n) = __floats2half2_rn(v0, v1);
                *(__half2*)(OutH + (size_t)(m + 8) * ldO + n) = __floats2half2_rn(v2, v3);
            } else {
                *(float2*)(OutF + (size_t)m * ldO + n) = make_float2(v0, v1);
                *(float2*)(OutF + (size_t)(m + 8) * ldO + n) = make_float2(v2, v3);
            }
        }
    }
#undef ASM_
#undef BSM_
}

// ---------------- fused flash attention ---------------------------------------
__global__ __launch_bounds__(128) void flash_kernel(const __half* __restrict__ qkv,
                                                    __half* __restrict__ y) {
    int qt = blockIdx.x, z = blockIdx.y;
    int b = z / Hc, h = z - b * Hc;
    const __half* base = qkv + (size_t)b * Tc * 3 * Cc;
    const __half* Qg = base + (size_t)qt * 64 * 3 * Cc + h * HDc;
    const __half* Kg = base + Cc + h * HDc;
    const __half* Vg = base + 2 * Cc + h * HDc;

    __shared__ __half Qs[64][72];
    __shared__ __half Ks[2][64][72];
    __shared__ __half Vs[2][64][72];

    int tid = threadIdx.x, lane = tid & 31, w = tid >> 5;
    int g = lane >> 2, tq = lane & 3;
    int lrow = lane & 15, lcol = (lane >> 4) * 8;

    for (int c = tid; c < 512; c += 128) {
        int r = c >> 3, c8 = (c & 7) * 8;
        cpasync16(&Qs[r][c8], Qg + (size_t)r * 3 * Cc + c8, 16);
        cpasync16(&Ks[0][r][c8], Kg + (size_t)r * 3 * Cc + c8, 16);
        cpasync16(&Vs[0][r][c8], Vg + (size_t)r * 3 * Cc + c8, 16);
    }
    CP_COMMIT();
    CP_WAIT0();
    __syncthreads();

    unsigned qf[4][4];
#pragma unroll
    for (int kc = 0; kc < 4; kc++)
        ldsm4(qf[kc][0], qf[kc][1], qf[kc][2], qf[kc][3],
              &Qs[w * 16 + lrow][kc * 16 + lcol]);

    float o[8][4];
#pragma unroll
    for (int i = 0; i < 8; i++)
#pragma unroll
        for (int r = 0; r < 4; r++) o[i][r] = 0.f;
    float m0 = -INFINITY, m1 = -INFINITY, l0 = 0.f, l1 = 0.f;

    int buf = 0;
    for (int j = 0; j <= qt; j++) {
        if (j + 1 <= qt) {
            for (int c = tid; c < 512; c += 128) {
                int r = c >> 3, c8 = (c & 7) * 8;
                cpasync16(&Ks[buf ^ 1][r][c8],
                          Kg + (size_t)((j + 1) * 64 + r) * 3 * Cc + c8, 16);
                cpasync16(&Vs[buf ^ 1][r][c8],
                          Vg + (size_t)((j + 1) * 64 + r) * 3 * Cc + c8, 16);
            }
            CP_COMMIT();
            CP_WAIT1();
        } else {
            CP_WAIT0();
        }
        __syncthreads();

        float s[8][4];
#pragma unroll
        for (int i = 0; i < 8; i++)
#pragma unroll
            for (int r = 0; r < 4; r++) s[i][r] = 0.f;
#pragma unroll
        for (int kc = 0; kc < 4; kc++) {
            unsigned kf[4][4];
#pragma unroll
            for (int nb = 0; nb < 4; nb++)
                ldsm4(kf[nb][0], kf[nb][1], kf[nb][2], kf[nb][3],
                      &Ks[buf][nb * 16 + lrow][kc * 16 + lcol]);
#pragma unroll
            for (int nb = 0; nb < 4; nb++) {
                mma16(s[nb * 2], qf[kc][0], qf[kc][1], qf[kc][2], qf[kc][3],
                      kf[nb][0], kf[nb][2]);
                mma16(s[nb * 2 + 1], qf[kc][0], qf[kc][1], qf[kc][2], qf[kc][3],
                      kf[nb][1], kf[nb][3]);
            }
        }
#pragma unroll
        for (int i = 0; i < 8; i++)
#pragma unroll
            for (int r = 0; r < 4; r++) s[i][r] *= 0.125f;
        if (j == qt) {
            int r0 = w * 16 + g, r1 = r0 + 8;
#pragma unroll
            for (int nt = 0; nt < 8; nt++) {
                int c0 = nt * 8 + tq * 2;
                if (c0 > r0) s[nt][0] = -1e30f;
                if (c0 + 1 > r0) s[nt][1] = -1e30f;
                if (c0 > r1) s[nt][2] = -1e30f;
                if (c0 + 1 > r1) s[nt][3] = -1e30f;
            }
        }
        float tm0 = -INFINITY, tm1 = -INFINITY;
#pragma unroll
        for (int nt = 0; nt < 8; nt++) {
            tm0 = fmaxf(tm0, fmaxf(s[nt][0], s[nt][1]));
            tm1 = fmaxf(tm1, fmaxf(s[nt][2], s[nt][3]));
        }
        tm0 = fmaxf(tm0, __shfl_xor_sync(0xffffffffu, tm0, 1));
        tm0 = fmaxf(tm0, __shfl_xor_sync(0xffffffffu, tm0, 2));
        tm1 = fmaxf(tm1, __shfl_xor_sync(0xffffffffu, tm1, 1));
        tm1 = fmaxf(tm1, __shfl_xor_sync(0xffffffffu, tm1, 2));
        float mn0 = fmaxf(m0, tm0), mn1 = fmaxf(m1, tm1);
        float a0 = __expf(m0 - mn0), a1 = __expf(m1 - mn1);
        m0 = mn0; m1 = mn1;

        float rs0 = 0.f, rs1 = 0.f;
        unsigned pa[4][4];
#pragma unroll
        for (int nt = 0; nt < 8; nt++) {
            float p0 = __expf(s[nt][0] - mn0);
            float p1 = __expf(s[nt][1] - mn0);
            float p2 = __expf(s[nt][2] - mn1);
            float p3 = __expf(s[nt][3] - mn1);
            rs0 += p0 + p1; rs1 += p2 + p3;
            int kc2 = nt >> 1, hh = (nt & 1) * 2;
            __half2 h01 = __floats2half2_rn(p0, p1);
            __half2 h23 = __floats2half2_rn(p2, p3);
            pa[kc2][hh]     = *(unsigned*)&h01;
            pa[kc2][hh + 1] = *(unsigned*)&h23;
        }
        rs0 += __shfl_xor_sync(0xffffffffu, rs0, 1);
        rs0 += __shfl_xor_sync(0xffffffffu, rs0, 2);
        rs1 += __shfl_xor_sync(0xffffffffu, rs1, 1);
        rs1 += __shfl_xor_sync(0xffffffffu, rs1, 2);
        l0 = l0 * a0 + rs0;
        l1 = l1 * a1 + rs1;
#pragma unroll
        for (int nt = 0; nt < 8; nt++) {
            o[nt][0] *= a0; o[nt][1] *= a0;
            o[nt][2] *= a1; o[nt][3] *= a1;
        }
#pragma unroll
        for (int kc2 = 0; kc2 < 4; kc2++) {
#pragma unroll
            for (int dn = 0; dn < 4; dn++) {
                unsigned v0, v1, v2, v3;
                ldsm4t(v0, v1, v2, v3,
                       &Vs[buf][kc2 * 16 + lrow][dn * 16 + lcol]);
                mma16(o[dn * 2], pa[kc2][0], pa[kc2][1], pa[kc2][2], pa[kc2][3], v0, v1);
                mma16(o[dn * 2 + 1], pa[kc2][0], pa[kc2][1], pa[kc2][2], pa[kc2][3], v2, v3);
            }
        }
        __syncthreads();
        buf ^= 1;
    }

    float il0 = 1.0f / l0, il1 = 1.0f / l1;
    int row0 = qt * 64 + w * 16 + g;
    __half* yp = y + ((size_t)(b * Tc + row0)) * Cc + h * HDc;
#pragma unroll
    for (int nt = 0; nt < 8; nt++) {
        int col = nt * 8 + tq * 2;
        *(__half2*)(yp + col) = __floats2half2_rn(o[nt][0] * il0, o[nt][1] * il0);
        *(__half2*)(yp + (size_t)8 * Cc + col) =
            __floats2half2_rn(o[nt][2] * il1, o[nt][3] * il1);
    }
}

// ---------------- head helpers ------------------------------------------------
__global__ void ww_kernel(const float* __restrict__ wte, float* __restrict__ ww) {
    __shared__ float sm[32];
    int v = blockIdx.x;
    const float* row = wte + (size_t)v * Cc;
    float s = 0.f;
    for (int c = threadIdx.x; c < Cc; c += blockDim.x) { float t = row[c]; s += t * t; }
    float tot = blockSum(s, sm);
    if (threadIdx.x == 0) ww[v] = tot;
}

// dist: ratio form, fp16 wx in / p staging, fp32 logits out.
__global__ __launch_bounds__(512) void dist_kernel(__half* __restrict__ wx,
                                                   float* __restrict__ out,
                                                   const float* __restrict__ ww,
                                                   const float* __restrict__ xx) {
    __shared__ float sm[32];
    int m = blockIdx.x;
    __half2* row2 = (__half2*)(wx + (size_t)m * Vc);
    float2* orow2 = (float2*)(out + (size_t)m * Vc);
    const float2* ww2 = (const float2*)ww;
    float xxm = xx[m];
    const int N2 = Vc / 2;

    float mn = INFINITY;
    for (int i = threadIdx.x; i < N2; i += 512) {
        float2 wv = ww2[i];
        float2 xv = __half22float2(row2[i]);
        float d0 = fmaf(-2.0f, xv.x, wv.x + xxm);
        float d1 = fmaf(-2.0f, xv.y, wv.y + xxm);
        mn = fminf(mn, fminf(d0, d1));
    }
    float MN = blockMin(mn, sm);
    float iMN = 1.0f / MN;

    float lsum = 0.f;
    for (int i = threadIdx.x; i < N2; i += 512) {
        float2 wv = ww2[i];
        float2 xv = __half22float2(row2[i]);
        float d0 = fmaf(-2.0f, xv.x, wv.x + xxm);
        float d1 = fmaf(-2.0f, xv.y, wv.y + xxm);
        float p0 = exp2f(-768.0f * __log2f(d0 * iMN));
        float p1 = exp2f(-768.0f * __log2f(d1 * iMN));
        lsum += p0 + p1;
        row2[i] = __floats2half2_rn(p0, p1);
    }
    float TOT = blockSum(lsum, sm);
    float invTot = 1.0f / TOT;
    const float floorp = 0.01f / 50304.0f;

    for (int i = threadIdx.x; i < N2; i += 512) {
        float2 pv = __half22float2(row2[i]);
        float q0 = __logf(fmaf(pv.x, invTot, floorp));
        float q1 = __logf(fmaf(pv.y, invTot, floorp));
        orow2[i] = make_float2(q0, q1);
    }
}

// ---------------- launch ------------------------------------------------------
extern "C" void kernel_launch(void* const* d_in, const int* in_sizes, int n_in,
                              void* d_out, int out_size) {
    const int*   idx    = (const int*)d_in[0];
    const float* wte    = (const float*)d_in[1];
    const float* wpe    = (const float*)d_in[2];
    const float* ln1_w  = (const float*)d_in[3];
    const float* ln1_b  = (const float*)d_in[4];
    const float* attn_w = (const float*)d_in[5];
    const float* attn_b = (const float*)d_in[6];
    const float* proj_w = (const float*)d_in[7];
    const float* proj_b = (const float*)d_in[8];
    const float* ln2_w  = (const float*)d_in[9];
    const float* ln2_b  = (const float*)d_in[10];
    const float* fc_w   = (const float*)d_in[11];
    const float* fc_b   = (const float*)d_in[12];
    const float* fc2_w  = (const float*)d_in[13];
    const float* fc2_b  = (const float*)d_in[14];
    const float* lnf_w  = (const float*)d_in[15];
    const float* lnf_b  = (const float*)d_in[16];
    float* out = (float*)d_out;

    float *x, *ww, *xx;
    __half *attn16, *proj16, *fcw16, *fc2w16, *wte16;
    __half *h16, *qkv16, *y16, *fcact16, *wx16;
    cudaGetSymbolAddress((void**)&x, g_x);
    cudaGetSymbolAddress((void**)&ww, g_ww);
    cudaGetSymbolAddress((void**)&xx, g_xx);
    cudaGetSymbolAddress((void**)&attn16, w_attn16);
    cudaGetSymbolAddress((void**)&proj16, w_proj16);
    cudaGetSymbolAddress((void**)&fcw16, w_fc16);
    cudaGetSymbolAddress((void**)&fc2w16, w_fc216);
    cudaGetSymbolAddress((void**)&wte16, w_wte16);
    cudaGetSymbolAddress((void**)&h16, g_h16);
    cudaGetSymbolAddress((void**)&qkv16, g_qkv16);
    cudaGetSymbolAddress((void**)&y16, g_y16);
    cudaGetSymbolAddress((void**)&fcact16, g_fc16);
    cudaGetSymbolAddress((void**)&wx16, g_wx16);

    const int S44 = 3 * (128 + 128) * 40 * 2;   // 61440 bytes -> 2 CTA/SM
    const int S22 = 3 * (64 + 64) * 40 * 2;     // 30720 bytes
    cudaFuncSetAttribute(gemm16<0, true, 4, 4>,
                         cudaFuncAttributeMaxDynamicSharedMemorySize, S44);
    cudaFuncSetAttribute(gemm16<2, true, 4, 4>,
                         cudaFuncAttributeMaxDynamicSharedMemorySize, S44);
    cudaFuncSetAttribute(gemm16<3, true, 4, 4>,
                         cudaFuncAttributeMaxDynamicSharedMemorySize, S44);
    cudaFuncSetAttribute(gemm16<1, false, 2, 2>,
                         cudaFuncAttributeMaxDynamicSharedMemorySize, S22);

    // weight conversions
    f2h_kernel<<<4096, 256>>>(attn_w, attn16, (long)Lc * 3 * Cc * Cc / 2);
    f2h_kernel<<<4096, 256>>>(proj_w, proj16, (long)Lc * Cc * Cc / 2);
    f2h_kernel<<<4096, 256>>>(fc_w, fcw16, (long)Lc * 4 * Cc * Cc / 2);
    f2h_kernel<<<4096, 256>>>(fc2_w, fc2w16, (long)Lc * Cc * 4 * Cc / 2);
    f2h_kernel<<<4096, 256>>>(wte, wte16, (long)Vc * Cc / 2);

    embed_kernel<<<Mc, 256>>>(idx, wte, wpe, x);
    ww_kernel<<<Vc, 128>>>(wte, ww);

    for (int l = 0; l < Lc; l++) {
        const float* l1w = ln1_w + (size_t)l * Cc;
        const float* l1b = ln1_b + (size_t)l * Cc;
        const __half* aw = attn16 + (size_t)l * 3 * Cc * Cc;
        const float* ab  = attn_b + (size_t)l * 3 * Cc;
        const __half* pw = proj16 + (size_t)l * Cc * Cc;
        const float* pb  = proj_b + (size_t)l * Cc;
        const float* l2w = ln2_w + (size_t)l * Cc;
        const float* l2b = ln2_b + (size_t)l * Cc;
        const __half* fw = fcw16 + (size_t)l * 4 * Cc * Cc;
        const float* fb  = fc_b + (size_t)l * 4 * Cc;
        const __half* f2w = fc2w16 + (size_t)l * Cc * 4 * Cc;
        const float* f2b = fc2_b + (size_t)l * Cc;

        ln_kernel<<<Mc / 4, 128>>>(x, h16, nullptr, l1w, l1b);

        // qkv16 = h @ attn_w^T + b   [1024, 2304]
        gemm16<0, true, 4, 4><<<dim3(18, 8), 256, S44>>>(
            h16, Cc, aw, Cc, ab, nullptr, qkv16, 3 * Cc, Cc, 3 * Cc);

        // fused attention -> y16
        flash_kernel<<<dim3(8, BHc), 128>>>(qkv16, y16);

        // x = x + y @ proj_w^T + proj_b   (fp32 out), 64x64 tiles: grid 192
        gemm16<1, false, 2, 2><<<dim3(12, 16), 256, S22>>>(
            y16, Cc, pw, Cc, pb, x, x, Cc, Cc, Cc);

        ln_kernel<<<Mc / 4, 128>>>(x, h16, nullptr, l2w, l2b);

        // fc16 = gelu(h @ fc_w^T + fc_b)  [1024, 3072]
        gemm16<2, true, 4, 4><<<dim3(24, 8), 256, S44>>>(
            h16, Cc, fw, Cc, fb, nullptr, fcact16, 4 * Cc, Cc, 4 * Cc);

        // x = x + fc @ fc2_w^T + fc2_b   64x64 tiles: grid 192
        gemm16<1, false, 2, 2><<<dim3(12, 16), 256, S22>>>(
            fcact16, 4 * Cc, f2w, 4 * Cc, f2b, x, x, Cc, 4 * Cc, Cc);
    }

    // final LN (+ fused xx) + head
    ln_kernel<<<Mc / 4, 128>>>(x, h16, xx, lnf_w, lnf_b);

    // wx16 = h @ wte^T  [1024, 50304] (fp16 out)
    gemm16<3, true, 4, 4><<<dim3(Vc / 128, 8), 256, S44>>>(
        h16, Cc, wte16, Cc, nullptr, nullptr, wx16, Vc, Cc, Vc);

    dist_kernel<<<Mc, 512>>>(wx16, out, ww, xx);
}

// round 17
// speedup vs baseline: 1.0682x; 1.0082x over previous
#include <cuda_runtime.h>
#include <cuda_fp16.h>
#include <math.h>
#include <stdint.h>

// Problem constants
#define Bc   2
#define Tc   512
#define Cc   768
#define Hc   12
#define HDc  64
#define Vc   50304
#define Lc   12
#define Mc   (Bc * Tc)          // 1024 rows
#define BHc  (Bc * Hc)          // 24
#define EPSc 1e-5f
#define GELU_Kc 0.7978845608028654f

// ---------------- scratch (device globals; no allocations allowed) ----------
__device__ float  g_x[Mc * Cc];
__device__ float  g_ww[Vc];
__device__ float  g_xx[Mc];

__device__ __half w_attn16[Lc * 3 * Cc * Cc];
__device__ __half w_proj16[Lc * Cc * Cc];
__device__ __half w_fc16[Lc * 4 * Cc * Cc];
__device__ __half w_fc216[Lc * Cc * 4 * Cc];
__device__ __half w_wte16[(size_t)Vc * Cc];

__device__ __half g_h16[Mc * Cc];
__device__ __half g_qkv16[Mc * 3 * Cc];
__device__ __half g_y16[Mc * Cc];
__device__ __half g_fc16[Mc * 4 * Cc];
__device__ __half g_wx16[(size_t)Mc * Vc];     // head logits staging (103MB)

// ---------------- reduction helpers -----------------------------------------
__device__ __forceinline__ float warpSum(float v) {
#pragma unroll
    for (int o = 16; o; o >>= 1) v += __shfl_xor_sync(0xffffffffu, v, o);
    return v;
}
__device__ __forceinline__ float warpMin(float v) {
#pragma unroll
    for (int o = 16; o; o >>= 1) v = fminf(v, __shfl_xor_sync(0xffffffffu, v, o));
    return v;
}
__device__ float blockSum(float v, float* sm) {
    int lane = threadIdx.x & 31, wid = threadIdx.x >> 5;
    int nw = blockDim.x >> 5;
    v = warpSum(v);
    if (lane == 0) sm[wid] = v;
    __syncthreads();
    float r = (threadIdx.x < nw) ? sm[threadIdx.x] : 0.0f;
    if (wid == 0) { r = warpSum(r); if (lane == 0) sm[0] = r; }
    __syncthreads();
    float out = sm[0];
    __syncthreads();
    return out;
}
__device__ float blockMin(float v, float* sm) {
    int lane = threadIdx.x & 31, wid = threadIdx.x >> 5;
    int nw = blockDim.x >> 5;
    v = warpMin(v);
    if (lane == 0) sm[wid] = v;
    __syncthreads();
    float r = (threadIdx.x < nw) ? sm[threadIdx.x] : INFINITY;
    if (wid == 0) { r = warpMin(r); if (lane == 0) sm[0] = r; }
    __syncthreads();
    float out = sm[0];
    __syncthreads();
    return out;
}

// ---------------- low-level asm helpers --------------------------------------
__device__ __forceinline__ void cpasync16(void* smem, const void* g, int sz) {
    unsigned a = (unsigned)__cvta_generic_to_shared(smem);
    asm volatile("cp.async.cg.shared.global [%0], [%1], 16, %2;\n"
                 :: "r"(a), "l"(g), "r"(sz));
}
#define CP_COMMIT() asm volatile("cp.async.commit_group;\n")
#define CP_WAIT0()  asm volatile("cp.async.wait_group 0;\n")
#define CP_WAIT1()  asm volatile("cp.async.wait_group 1;\n")

__device__ __forceinline__ void ldsm4(unsigned& r0, unsigned& r1, unsigned& r2,
                                      unsigned& r3, const __half* p) {
    unsigned a = (unsigned)__cvta_generic_to_shared(p);
    asm volatile("ldmatrix.sync.aligned.m8n8.x4.shared.b16 {%0,%1,%2,%3}, [%4];\n"
                 : "=r"(r0), "=r"(r1), "=r"(r2), "=r"(r3) : "r"(a));
}
__device__ __forceinline__ void ldsm4t(unsigned& r0, unsigned& r1, unsigned& r2,
                                       unsigned& r3, const __half* p) {
    unsigned a = (unsigned)__cvta_generic_to_shared(p);
    asm volatile("ldmatrix.sync.aligned.m8n8.x4.trans.shared.b16 {%0,%1,%2,%3}, [%4];\n"
                 : "=r"(r0), "=r"(r1), "=r"(r2), "=r"(r3) : "r"(a));
}
__device__ __forceinline__ void mma16(float* c, unsigned a0, unsigned a1,
                                      unsigned a2, unsigned a3,
                                      unsigned b0, unsigned b1) {
    asm volatile(
        "mma.sync.aligned.m16n8k16.row.col.f32.f16.f16.f32 "
        "{%0,%1,%2,%3},{%4,%5,%6,%7},{%8,%9},{%0,%1,%2,%3};\n"
        : "+f"(c[0]), "+f"(c[1]), "+f"(c[2]), "+f"(c[3])
        : "r"(a0), "r"(a1), "r"(a2), "r"(a3), "r"(b0), "r"(b1));
}

__device__ __forceinline__ float geluf(float t) {
    return 0.5f * t * (1.0f + tanhf(GELU_Kc * (t + 0.044715f * t * t * t)));
}

// ---------------- f32 -> f16 convert ------------------------------------------
__global__ void f2h_kernel(const float* __restrict__ src, __half* __restrict__ dst,
                           long n2) {
    long i = (long)blockIdx.x * blockDim.x + threadIdx.x;
    long stride = (long)gridDim.x * blockDim.x;
    const float2* s2 = (const float2*)src;
    __half2* d2 = (__half2*)dst;
    for (; i < n2; i += stride) {
        float2 v = s2[i];
        d2[i] = __floats2half2_rn(v.x, v.y);
    }
}

// ---------------- embedding ---------------------------------------------------
__global__ void embed_kernel(const int* __restrict__ idx,
                             const float* __restrict__ wte,
                             const float* __restrict__ wpe,
                             float* __restrict__ x) {
    int m = blockIdx.x;
    int t = m % Tc;
    int row = idx[m];
    const float* wr = wte + (size_t)row * Cc;
    const float* pr = wpe + (size_t)t * Cc;
    float* xr = x + (size_t)m * Cc;
    for (int c = threadIdx.x; c < Cc; c += blockDim.x)
        xr[c] = wr[c] + pr[c];
}

// ---------------- layernorm: warp-per-row -------------------------------------
__global__ __launch_bounds__(128) void ln_kernel(
    const float* __restrict__ in, __half* __restrict__ outh,
    float* __restrict__ xx,
    const float* __restrict__ w, const float* __restrict__ b) {
    int warp = threadIdx.x >> 5, lane = threadIdx.x & 31;
    int m = blockIdx.x * 4 + warp;
    const float4* r4 = (const float4*)(in + (size_t)m * Cc);
    const float4* w4 = (const float4*)w;
    const float4* b4 = (const float4*)b;

    float4 v[6];
    float s = 0.f, ss = 0.f;
#pragma unroll
    for (int i = 0; i < 6; i++) {
        v[i] = r4[lane + 32 * i];
        s += v[i].x + v[i].y + v[i].z + v[i].w;
        ss += v[i].x * v[i].x + v[i].y * v[i].y + v[i].z * v[i].z + v[i].w * v[i].w;
    }
    s = warpSum(s);
    ss = warpSum(ss);
    const float invC = 1.0f / Cc;
    float mean = s * invC;
    float var = ss * invC - mean * mean;
    float rstd = rsqrtf(var + EPSc);

    __half2* o2 = (__half2*)(outh + (size_t)m * Cc);
    float s2 = 0.f;
#pragma unroll
    for (int i = 0; i < 6; i++) {
        float4 wv = w4[lane + 32 * i];
        float4 bv = b4[lane + 32 * i];
        float a0 = (v[i].x - mean) * rstd * wv.x + bv.x;
        float a1 = (v[i].y - mean) * rstd * wv.y + bv.y;
        float a2 = (v[i].z - mean) * rstd * wv.z + bv.z;
        float a3 = (v[i].w - mean) * rstd * wv.w + bv.w;
        o2[2 * (lane + 32 * i)]     = __floats2half2_rn(a0, a1);
        o2[2 * (lane + 32 * i) + 1] = __floats2half2_rn(a2, a3);
        s2 += a0 * a0 + a1 * a1 + a2 * a2 + a3 * a3;
    }
    if (xx) {
        s2 = warpSum(s2);
        if (lane == 0) xx[m] = s2;
    }
}

// ---------------- 3-stage pipelined fp16 MMA GEMM (NT) ------------------------
// Tile: BM = MI*32, BN = NI*32.  8 warps = 2 (m) x 4 (n).  smem 61KB -> 2 CTA/SM.
template <int MODE, bool OUTH, int MI, int NI>
__global__ __launch_bounds__(256) void gemm16(
    const __half* __restrict__ A, long ldA,
    const __half* __restrict__ B, long ldB,
    const float* __restrict__ bias, const float* __restrict__ res,
    void* __restrict__ Out, long ldO,
    int K, int Nr) {
    const int BM = MI * 32, BN = NI * 32, BK = 32, BK8 = BK + 8;
    const int NB = (NI + 1) / 2;
    int bm = blockIdx.y * BM;
    int bn = blockIdx.x * BN;

    extern __shared__ unsigned char dyn_raw[];
    __half* As = (__half*)dyn_raw;
    __half* Bs = As + 3 * BM * BK8;
#define ASM_(s, r, c) As[((s) * BM + (r)) * BK8 + (c)]
#define BSM_(s, r, c) Bs[((s) * BN + (r)) * BK8 + (c)]

    const float* Res = (MODE == 1) ? res : nullptr;
    float*  OutF = OUTH ? nullptr : (float*)Out;
    __half* OutH = OUTH ? (__half*)Out : nullptr;

    int tid = threadIdx.x;
    int lane = tid & 31;
    int wid = tid >> 5;
    int g = lane >> 2;
    int tq = lane & 3;
    int wm = (wid & 1) * (MI * 16);
    int wn = (wid >> 1) * (NI * 8);
    int lrow = lane & 15;
    int lcol = (lane >> 4) * 8;

    int lr = tid >> 2;
    int lk = (tid & 3) * 8;

    const __half* aP0 = A + (size_t)(bm + lr) * ldA + lk;
    const __half* aP1 = aP0 + (size_t)64 * ldA;
    int brow0 = bn + lr, brow1 = bn + lr + 64;
    int szB0 = (brow0 < Nr) ? 16 : 0;
    int szB1 = (brow1 < Nr) ? 16 : 0;
    const __half* bP0 = B + (size_t)(szB0 ? brow0 : 0) * ldB + lk;
    const __half* bP1 = B + (size_t)(szB1 ? brow1 : 0) * ldB + lk;

    float acc[MI][NI][4];
#pragma unroll
    for (int i = 0; i < MI; i++)
#pragma unroll
        for (int j = 0; j < NI; j++)
#pragma unroll
            for (int r = 0; r < 4; r++) acc[i][j][r] = 0.f;

    int nk = K / BK;

    auto load_tile = [&](int st, int kt) {
        int k0 = kt * BK;
        cpasync16(&ASM_(st, lr, lk), aP0 + k0, 16);
        if (MI == 4) cpasync16(&ASM_(st, lr + 64, lk), aP1 + k0, 16);
        cpasync16(&BSM_(st, lr, lk), bP0 + k0, szB0);
        if (NI == 4) cpasync16(&BSM_(st, lr + 64, lk), bP1 + k0, szB1);
        CP_COMMIT();
    };

    load_tile(0, 0);
    if (nk > 1) load_tile(1, 1);

    for (int kt = 0; kt < nk; kt++) {
        if (kt + 1 < nk) { CP_WAIT1(); } else { CP_WAIT0(); }
        __syncthreads();
        if (kt + 2 < nk) load_tile((kt + 2) % 3, kt + 2);
        int buf = kt % 3;

#pragma unroll
        for (int kp = 0; kp < 2; kp++) {
            unsigned af[MI][4];
#pragma unroll
            for (int mi = 0; mi < MI; mi++)
                ldsm4(af[mi][0], af[mi][1], af[mi][2], af[mi][3],
                      &ASM_(buf, wm + mi * 16 + lrow, kp * 16 + lcol));
            unsigned bf[NB][4];
#pragma unroll
            for (int nb = 0; nb < NB; nb++)
                ldsm4(bf[nb][0], bf[nb][1], bf[nb][2], bf[nb][3],
                      &BSM_(buf, wn + nb * 16 + lrow, kp * 16 + lcol));
#pragma unroll
            for (int mi = 0; mi < MI; mi++)
#pragma unroll
                for (int ni = 0; ni < NI; ni++) {
                    int nb = ni >> 1, wh = ni & 1;
                    mma16(acc[mi][ni],
                          af[mi][0], af[mi][1], af[mi][2], af[mi][3],
                          bf[nb][wh ? 1 : 0], bf[nb][wh ? 3 : 2]);
                }
        }
    }

#pragma unroll
    for (int mi = 0; mi < MI; mi++) {
        int m = bm + wm + mi * 16 + g;
#pragma unroll
        for (int ni = 0; ni < NI; ni++) {
            int n = bn + wn + ni * 8 + tq * 2;
            if (n >= Nr) continue;
            float v0 = acc[mi][ni][0], v1 = acc[mi][ni][1];
            float v2 = acc[mi][ni][2], v3 = acc[mi][ni][3];
            if (MODE != 3) {
                float b0 = bias[n], b1 = bias[n + 1];
                v0 += b0; v1 += b1; v2 += b0; v3 += b1;
            }
            if (MODE == 1) {
                v0 += Res[(size_t)m * ldO + n];
                v1 += Res[(size_t)m * ldO + n + 1];
                v2 += Res[(size_t)(m + 8) * ldO + n];
                v3 += Res[(size_t)(m + 8) * ldO + n + 1];
            }
            if (MODE == 2) { v0 = geluf(v0); v1 = geluf(v1); v2 = geluf(v2); v3 = geluf(v3); }
            if (OUTH) {
                *(__half2*)(OutH + (size_t)m * ldO + n) = __floats2half2_rn(v0, v1);
                *(__half2*)(OutH + (size_t)(m + 8) * ldO + n) = __floats2half2_rn(v2, v3);
            } else {
                *(float2*)(OutF + (size_t)m * ldO + n) = make_float2(v0, v1);
                *(float2*)(OutF + (size_t)(m + 8) * ldO + n) = make_float2(v2, v3);
            }
        }
    }
#undef ASM_
#undef BSM_
}

// ---------------- fused flash attention ---------------------------------------
__global__ __launch_bounds__(128) void flash_kernel(const __half* __restrict__ qkv,
                                                    __half* __restrict__ y) {
    int qt = blockIdx.x, z = blockIdx.y;
    int b = z / Hc, h = z - b * Hc;
    const __half* base = qkv + (size_t)b * Tc * 3 * Cc;
    const __half* Qg = base + (size_t)qt * 64 * 3 * Cc + h * HDc;
    const __half* Kg = base + Cc + h * HDc;
    const __half* Vg = base + 2 * Cc + h * HDc;

    __shared__ __half Qs[64][72];
    __shared__ __half Ks[2][64][72];
    __shared__ __half Vs[2][64][72];

    int tid = threadIdx.x, lane = tid & 31, w = tid >> 5;
    int g = lane >> 2, tq = lane & 3;
    int lrow = lane & 15, lcol = (lane >> 4) * 8;

    for (int c = tid; c < 512; c += 128) {
        int r = c >> 3, c8 = (c & 7) * 8;
        cpasync16(&Qs[r][c8], Qg + (size_t)r * 3 * Cc + c8, 16);
        cpasync16(&Ks[0][r][c8], Kg + (size_t)r * 3 * Cc + c8, 16);
        cpasync16(&Vs[0][r][c8], Vg + (size_t)r * 3 * Cc + c8, 16);
    }
    CP_COMMIT();
    CP_WAIT0();
    __syncthreads();

    unsigned qf[4][4];
#pragma unroll
    for (int kc = 0; kc < 4; kc++)
        ldsm4(qf[kc][0], qf[kc][1], qf[kc][2], qf[kc][3],
              &Qs[w * 16 + lrow][kc * 16 + lcol]);

    float o[8][4];
#pragma unroll
    for (int i = 0; i < 8; i++)
#pragma unroll
        for (int r = 0; r < 4; r++) o[i][r] = 0.f;
    float m0 = -INFINITY, m1 = -INFINITY, l0 = 0.f, l1 = 0.f;

    int buf = 0;
    for (int j = 0; j <= qt; j++) {
        if (j + 1 <= qt) {
            for (int c = tid; c < 512; c += 128) {
                int r = c >> 3, c8 = (c & 7) * 8;
                cpasync16(&Ks[buf ^ 1][r][c8],
                          Kg + (size_t)((j + 1) * 64 + r) * 3 * Cc + c8, 16);
                cpasync16(&Vs[buf ^ 1][r][c8],
                          Vg + (size_t)((j + 1) * 64 + r) * 3 * Cc + c8, 16);
            }
            CP_COMMIT();
            CP_WAIT1();
        } else {
            CP_WAIT0();
        }
        __syncthreads();

        float s[8][4];
#pragma unroll
        for (int i = 0; i < 8; i++)
#pragma unroll
            for (int r = 0; r < 4; r++) s[i][r] = 0.f;
#pragma unroll
        for (int kc = 0; kc < 4; kc++) {
            unsigned kf[4][4];
#pragma unroll
            for (int nb = 0; nb < 4; nb++)
                ldsm4(kf[nb][0], kf[nb][1], kf[nb][2], kf[nb][3],
                      &Ks[buf][nb * 16 + lrow][kc * 16 + lcol]);
#pragma unroll
            for (int nb = 0; nb < 4; nb++) {
                mma16(s[nb * 2], qf[kc][0], qf[kc][1], qf[kc][2], qf[kc][3],
                      kf[nb][0], kf[nb][2]);
                mma16(s[nb * 2 + 1], qf[kc][0], qf[kc][1], qf[kc][2], qf[kc][3],
                      kf[nb][1], kf[nb][3]);
            }
        }
#pragma unroll
        for (int i = 0; i < 8; i++)
#pragma unroll
            for (int r = 0; r < 4; r++) s[i][r] *= 0.125f;
        if (j == qt) {
            int r0 = w * 16 + g, r1 = r0 + 8;
#pragma unroll
            for (int nt = 0; nt < 8; nt++) {
                int c0 = nt * 8 + tq * 2;
                if (c0 > r0) s[nt][0] = -1e30f;
                if (c0 + 1 > r0) s[nt][1] = -1e30f;
                if (c0 > r1) s[nt][2] = -1e30f;
                if (c0 + 1 > r1) s[nt][3] = -1e30f;
            }
        }
        float tm0 = -INFINITY, tm1 = -INFINITY;
#pragma unroll
        for (int nt = 0; nt < 8; nt++) {
            tm0 = fmaxf(tm0, fmaxf(s[nt][0], s[nt][1]));
            tm1 = fmaxf(tm1, fmaxf(s[nt][2], s[nt][3]));
        }
        tm0 = fmaxf(tm0, __shfl_xor_sync(0xffffffffu, tm0, 1));
        tm0 = fmaxf(tm0, __shfl_xor_sync(0xffffffffu, tm0, 2));
        tm1 = fmaxf(tm1, __shfl_xor_sync(0xffffffffu, tm1, 1));
        tm1 = fmaxf(tm1, __shfl_xor_sync(0xffffffffu, tm1, 2));
        float mn0 = fmaxf(m0, tm0), mn1 = fmaxf(m1, tm1);
        float a0 = __expf(m0 - mn0), a1 = __expf(m1 - mn1);
        m0 = mn0; m1 = mn1;

        float rs0 = 0.f, rs1 = 0.f;
        unsigned pa[4][4];
#pragma unroll
        for (int nt = 0; nt < 8; nt++) {
            float p0 = __expf(s[nt][0] - mn0);
            float p1 = __expf(s[nt][1] - mn0);
            float p2 = __expf(s[nt][2] - mn1);
            float p3 = __expf(s[nt][3] - mn1);
            rs0 += p0 + p1; rs1 += p2 + p3;
            int kc2 = nt >> 1, hh = (nt & 1) * 2;
            __half2 h01 = __floats2half2_rn(p0, p1);
            __half2 h23 = __floats2half2_rn(p2, p3);
            pa[kc2][hh]     = *(unsigned*)&h01;
            pa[kc2][hh + 1] = *(unsigned*)&h23;
        }
        rs0 += __shfl_xor_sync(0xffffffffu, rs0, 1);
        rs0 += __shfl_xor_sync(0xffffffffu, rs0, 2);
        rs1 += __shfl_xor_sync(0xffffffffu, rs1, 1);
        rs1 += __shfl_xor_sync(0xffffffffu, rs1, 2);
        l0 = l0 * a0 + rs0;
        l1 = l1 * a1 + rs1;
#pragma unroll
        for (int nt = 0; nt < 8; nt++) {
            o[nt][0] *= a0; o[nt][1] *= a0;
            o[nt][2] *= a1; o[nt][3] *= a1;
        }
#pragma unroll
        for (int kc2 = 0; kc2 < 4; kc2++) {
#pragma unroll
            for (int dn = 0; dn < 4; dn++) {
                unsigned v0, v1, v2, v3;
                ldsm4t(v0, v1, v2, v3,
                       &Vs[buf][kc2 * 16 + lrow][dn * 16 + lcol]);
                mma16(o[dn * 2], pa[kc2][0], pa[kc2][1], pa[kc2][2], pa[kc2][3], v0, v1);
                mma16(o[dn * 2 + 1], pa[kc2][0], pa[kc2][1], pa[kc2][2], pa[kc2][3], v2, v3);
            }
        }
        __syncthreads();
        buf ^= 1;
    }

    float il0 = 1.0f / l0, il1 = 1.0f / l1;
    int row0 = qt * 64 + w * 16 + g;
    __half* yp = y + ((size_t)(b * Tc + row0)) * Cc + h * HDc;
#pragma unroll
    for (int nt = 0; nt < 8; nt++) {
        int col = nt * 8 + tq * 2;
        *(__half2*)(yp + col) = __floats2half2_rn(o[nt][0] * il0, o[nt][1] * il0);
        *(__half2*)(yp + (size_t)8 * Cc + col) =
            __floats2half2_rn(o[nt][2] * il1, o[nt][3] * il1);
    }
}

// ---------------- head helpers ------------------------------------------------
__global__ void ww_kernel(const float* __restrict__ wte, float* __restrict__ ww) {
    __shared__ float sm[32];
    int v = blockIdx.x;
    const float* row = wte + (size_t)v * Cc;
    float s = 0.f;
    for (int c = threadIdx.x; c < Cc; c += blockDim.x) { float t = row[c]; s += t * t; }
    float tot = blockSum(s, sm);
    if (threadIdx.x == 0) ww[v] = tot;
}

// dist: smem-staged (wx row cached in shared; p staged in-place in shared).
__global__ __launch_bounds__(512) void dist_kernel(const __half* __restrict__ wx,
                                                   float* __restrict__ out,
                                                   const float* __restrict__ ww,
                                                   const float* __restrict__ xx) {
    __shared__ float sm[32];
    extern __shared__ unsigned char dyn_raw[];
    __half2* sp2 = (__half2*)dyn_raw;
    int m = blockIdx.x;
    const __half2* row2 = (const __half2*)(wx + (size_t)m * Vc);
    float2* orow2 = (float2*)(out + (size_t)m * Vc);
    const float2* ww2 = (const float2*)ww;
    float xxm = xx[m];
    const int N2 = Vc / 2;

    float mn = INFINITY;
    for (int i = threadIdx.x; i < N2; i += 512) {
        __half2 h = row2[i];
        sp2[i] = h;
        float2 wv = ww2[i];
        float2 xv = __half22float2(h);
        float d0 = fmaf(-2.0f, xv.x, wv.x + xxm);
        float d1 = fmaf(-2.0f, xv.y, wv.y + xxm);
        mn = fminf(mn, fminf(d0, d1));
    }
    float MN = blockMin(mn, sm);
    float iMN = 1.0f / MN;

    float lsum = 0.f;
    for (int i = threadIdx.x; i < N2; i += 512) {
        float2 wv = ww2[i];
        float2 xv = __half22float2(sp2[i]);
        float d0 = fmaf(-2.0f, xv.x, wv.x + xxm);
        float d1 = fmaf(-2.0f, xv.y, wv.y + xxm);
        float p0 = exp2f(-768.0f * __log2f(d0 * iMN));
        float p1 = exp2f(-768.0f * __log2f(d1 * iMN));
        lsum += p0 + p1;
        sp2[i] = __floats2half2_rn(p0, p1);
    }
    float TOT = blockSum(lsum, sm);
    float invTot = 1.0f / TOT;
    const float floorp = 0.01f / 50304.0f;

    for (int i = threadIdx.x; i < N2; i += 512) {
        float2 pv = __half22float2(sp2[i]);
        float q0 = __logf(fmaf(pv.x, invTot, floorp));
        float q1 = __logf(fmaf(pv.y, invTot, floorp));
        orow2[i] = make_float2(q0, q1);
    }
}

// ---------------- launch ------------------------------------------------------
extern "C" void kernel_launch(void* const* d_in, const int* in_sizes, int n_in,
                              void* d_out, int out_size) {
    const int*   idx    = (const int*)d_in[0];
    const float* wte    = (const float*)d_in[1];
    const float* wpe    = (const float*)d_in[2];
    const float* ln1_w  = (const float*)d_in[3];
    const float* ln1_b  = (const float*)d_in[4];
    const float* attn_w = (const float*)d_in[5];
    const float* attn_b = (const float*)d_in[6];
    const float* proj_w = (const float*)d_in[7];
    const float* proj_b = (const float*)d_in[8];
    const float* ln2_w  = (const float*)d_in[9];
    const float* ln2_b  = (const float*)d_in[10];
    const float* fc_w   = (const float*)d_in[11];
    const float* fc_b   = (const float*)d_in[12];
    const float* fc2_w  = (const float*)d_in[13];
    const float* fc2_b  = (const float*)d_in[14];
    const float* lnf_w  = (const float*)d_in[15];
    const float* lnf_b  = (const float*)d_in[16];
    float* out = (float*)d_out;

    float *x, *ww, *xx;
    __half *attn16, *proj16, *fcw16, *fc2w16, *wte16;
    __half *h16, *qkv16, *y16, *fcact16, *wx16;
    cudaGetSymbolAddress((void**)&x, g_x);
    cudaGetSymbolAddress((void**)&ww, g_ww);
    cudaGetSymbolAddress((void**)&xx, g_xx);
    cudaGetSymbolAddress((void**)&attn16, w_attn16);
    cudaGetSymbolAddress((void**)&proj16, w_proj16);
    cudaGetSymbolAddress((void**)&fcw16, w_fc16);
    cudaGetSymbolAddress((void**)&fc2w16, w_fc216);
    cudaGetSymbolAddress((void**)&wte16, w_wte16);
    cudaGetSymbolAddress((void**)&h16, g_h16);
    cudaGetSymbolAddress((void**)&qkv16, g_qkv16);
    cudaGetSymbolAddress((void**)&y16, g_y16);
    cudaGetSymbolAddress((void**)&fcact16, g_fc16);
    cudaGetSymbolAddress((void**)&wx16, g_wx16);

    const int S44 = 3 * (128 + 128) * 40 * 2;   // 61440 bytes -> 2 CTA/SM
    const int S22 = 3 * (64 + 64) * 40 * 2;     // 30720 bytes
    cudaFuncSetAttribute(gemm16<0, true, 4, 4>,
                         cudaFuncAttributeMaxDynamicSharedMemorySize, S44);
    cudaFuncSetAttribute(gemm16<2, true, 4, 4>,
                         cudaFuncAttributeMaxDynamicSharedMemorySize, S44);
    cudaFuncSetAttribute(gemm16<3, true, 4, 4>,
                         cudaFuncAttributeMaxDynamicSharedMemorySize, S44);
    cudaFuncSetAttribute(gemm16<1, false, 2, 2>,
                         cudaFuncAttributeMaxDynamicSharedMemorySize, S22);
    cudaFuncSetAttribute(dist_kernel,
                         cudaFuncAttributeMaxDynamicSharedMemorySize, Vc * 2);

    // weight conversions
    f2h_kernel<<<4096, 256>>>(attn_w, attn16, (long)Lc * 3 * Cc * Cc / 2);
    f2h_kernel<<<4096, 256>>>(proj_w, proj16, (long)Lc * Cc * Cc / 2);
    f2h_kernel<<<4096, 256>>>(fc_w, fcw16, (long)Lc * 4 * Cc * Cc / 2);
    f2h_kernel<<<4096, 256>>>(fc2_w, fc2w16, (long)Lc * Cc * 4 * Cc / 2);
    f2h_kernel<<<4096, 256>>>(wte, wte16, (long)Vc * Cc / 2);

    embed_kernel<<<Mc, 256>>>(idx, wte, wpe, x);
    ww_kernel<<<Vc, 128>>>(wte, ww);

    for (int l = 0; l < Lc; l++) {
        const float* l1w = ln1_w + (size_t)l * Cc;
        const float* l1b = ln1_b + (size_t)l * Cc;
        const __half* aw = attn16 + (size_t)l * 3 * Cc * Cc;
        const float* ab  = attn_b + (size_t)l * 3 * Cc;
        const __half* pw = proj16 + (size_t)l * Cc * Cc;
        const float* pb  = proj_b + (size_t)l * Cc;
        const float* l2w = ln2_w + (size_t)l * Cc;
        const float* l2b = ln2_b + (size_t)l * Cc;
        const __half* fw = fcw16 + (size_t)l * 4 * Cc * Cc;
        const float* fb  = fc_b + (size_t)l * 4 * Cc;
        const __half* f2w = fc2w16 + (size_t)l * Cc * 4 * Cc;
        const float* f2b = fc2_b + (size_t)l * Cc;

        ln_kernel<<<Mc / 4, 128>>>(x, h16, nullptr, l1w, l1b);

        // qkv16 = h @ attn_w^T + b   [1024, 2304]
        gemm16<0, true, 4, 4><<<dim3(18, 8), 256, S44>>>(
            h16, Cc, aw, Cc, ab, nullptr, qkv16, 3 * Cc, Cc, 3 * Cc);

        // fused attention -> y16
        flash_kernel<<<dim3(8, BHc), 128>>>(qkv16, y16);

        // x = x + y @ proj_w^T + proj_b   (fp32 out), 64x64 tiles: grid 192
        gemm16<1, false, 2, 2><<<dim3(12, 16), 256, S22>>>(
            y16, Cc, pw, Cc, pb, x, x, Cc, Cc, Cc);

        ln_kernel<<<Mc / 4, 128>>>(x, h16, nullptr, l2w, l2b);

        // fc16 = gelu(h @ fc_w^T + fc_b)  [1024, 3072]
        gemm16<2, true, 4, 4><<<dim3(24, 8), 256, S44>>>(
            h16, Cc, fw, Cc, fb, nullptr, fcact16, 4 * Cc, Cc, 4 * Cc);

        // x = x + fc @ fc2_w^T + fc2_b   64x64 tiles: grid 192
        gemm16<1, false, 2, 2><<<dim3(12, 16), 256, S22>>>(
            fcact16, 4 * Cc, f2w, 4 * Cc, f2b, x, x, Cc, 4 * Cc, Cc);
    }

    // final LN (+ fused xx) + head
    ln_kernel<<<Mc / 4, 128>>>(x, h16, xx, lnf_w, lnf_b);

    // wx16 = h @ wte^T  [1024, 50304] (fp16 out)
    gemm16<3, true, 4, 4><<<dim3(Vc / 128, 8), 256, S44>>>(
        h16, Cc, wte16, Cc, nullptr, nullptr, wx16, Vc, Cc, Vc);

    dist_kernel<<<Mc, 512, Vc * 2>>>(wx16, out, ww, xx);
}